// round 1
// baseline (speedup 1.0000x reference)
#include <cuda_runtime.h>

#define H   224
#define W   224
#define HW  (224*224)
#define C   21
#define K   48
#define H2  67
#define W2  67
#define HW2 (67*67)
#define MH  56
#define MW  56
#define EPSF 1e-8f
#define W1F  0.3f

// ---------------- device scratch (no allocations allowed) ----------------
__device__ __align__(16) float g_buf0[C*HW];
__device__ __align__(16) float g_buf1[C*HW];
__device__ __align__(16) float g_aff [HW*K];     // pixel-major [p][k]
__device__ __align__(16) float g_imgs2[3*HW2];
__device__ __align__(16) float g_aff2p[HW2*K];   // pixel-major [p2][k]
__device__ __align__(16) float g_pos[K];

__device__ __forceinline__ int clampi(int v, int lo, int hi) {
    return v < lo ? lo : (v > hi ? hi : v);
}

// ---------------- pos softmax (constant 48-vector) ----------------
__global__ void pos_kernel() {
    if (threadIdx.x != 0 || blockIdx.x != 0) return;
    const float s2 = sqrtf(2.0f);
    const float base[8] = {s2, 1.f, s2, 1.f, 1.f, s2, 1.f, s2};
    const int DD[6] = {1, 2, 4, 8, 12, 24};
    float pos[K];
    float sum = 0.f;
    for (int di = 0; di < 6; di++)
        for (int o = 0; o < 8; o++) {
            float v = base[o] * (float)DD[di];
            pos[di*8+o] = v; sum += v;
        }
    float mean = sum / 48.f, ss = 0.f;
    for (int k = 0; k < K; k++) { float d = pos[k] - mean; ss += d * d; }
    float sd = sqrtf(ss / 47.f);
    float mx = -1e30f;
    for (int k = 0; k < K; k++) {
        float t = pos[k] / ((sd + EPSF) * W1F);
        pos[k] = -t * t;
        mx = fmaxf(mx, pos[k]);
    }
    float es = 0.f;
    for (int k = 0; k < K; k++) { pos[k] = expf(pos[k] - mx); es += pos[k]; }
    float inv = 1.f / es;
    for (int k = 0; k < K; k++) g_pos[k] = pos[k] * inv;
}

// ---------------- bilinear upsample masks 56 -> 224 into g_buf0 ----------------
__global__ void upmask_kernel(const float* __restrict__ m) {
    int idx = blockIdx.x * blockDim.x + threadIdx.x;
    if (idx >= C*HW) return;
    int c = idx / HW;
    int p = idx - c * HW;
    int y = p / W, x = p - y * W;
    float fy = (float)y * (55.f / 223.f);
    int y0 = (int)fy; float wy = fy - (float)y0; int y1 = min(y0 + 1, 55);
    float fx = (float)x * (55.f / 223.f);
    int x0 = (int)fx; float wx = fx - (float)x0; int x1 = min(x0 + 1, 55);
    const float* mc = m + c * MH * MW;
    float r0 = mc[y0*MW+x0] * (1.f - wy) + mc[y1*MW+x0] * wy;
    float r1 = mc[y0*MW+x1] * (1.f - wy) + mc[y1*MW+x1] * wy;
    g_buf0[idx] = r0 * (1.f - wx) + r1 * wx;
}

// ---------------- bilinear downsample imgs 224 -> 67 ----------------
__global__ void downimg_kernel(const float* __restrict__ imgs) {
    int idx = blockIdx.x * blockDim.x + threadIdx.x;
    if (idx >= 3*HW2) return;
    int c = idx / HW2;
    int p = idx - c * HW2;
    int y = p / W2, x = p - y * W2;
    float fy = (float)y * (223.f / 66.f);
    int y0 = (int)fy; float wy = fy - (float)y0; int y1 = min(y0 + 1, 223);
    float fx = (float)x * (223.f / 66.f);
    int x0 = (int)fx; float wx = fx - (float)x0; int x1 = min(x0 + 1, 223);
    const float* ic = imgs + c * HW;
    float r0 = ic[y0*W+x0] * (1.f - wy) + ic[y1*W+x0] * wy;
    float r1 = ic[y0*W+x1] * (1.f - wy) + ic[y1*W+x1] * wy;
    g_imgs2[idx] = r0 * (1.f - wx) + r1 * wx;
}

// ---------------- low-res affinity (no W1, no softmax yet), pixel-major out ----
__global__ void aff2_kernel() {
    int p = blockIdx.x * blockDim.x + threadIdx.x;
    if (p >= HW2) return;
    int y = p / W2, x = p - y * W2;
    float t[K];
    #pragma unroll
    for (int k = 0; k < K; k++) t[k] = 0.f;

    const int DD[6] = {1, 2, 4, 8, 12, 24};
    const int DY[8] = {-1,-1,-1, 0, 0, 1, 1, 1};
    const int DX[8] = {-1, 0, 1,-1, 1,-1, 0, 1};

    for (int c = 0; c < 3; c++) {
        const float* im = g_imgs2 + c * HW2;
        float ctr = im[p];
        float sum = 0.f, ss = 0.f;
        #pragma unroll
        for (int di = 0; di < 6; di++) {
            #pragma unroll
            for (int o = 0; o < 8; o++) {
                int yy = clampi(y + DY[o]*DD[di], 0, H2-1);
                int xx = clampi(x + DX[o]*DD[di], 0, W2-1);
                float v = im[yy*W2+xx];
                sum += v; ss = fmaf(v, v, ss);
            }
        }
        float mean = sum * (1.f/48.f);
        float var  = fmaxf((ss - sum * mean) * (1.f/47.f), 0.f);
        float inv  = 1.f / (sqrtf(var) + EPSF);
        float inv2 = inv * inv;
        #pragma unroll
        for (int di = 0; di < 6; di++) {
            #pragma unroll
            for (int o = 0; o < 8; o++) {
                int yy = clampi(y + DY[o]*DD[di], 0, H2-1);
                int xx = clampi(x + DX[o]*DD[di], 0, W2-1);
                float d = im[yy*W2+xx] - ctr;
                t[di*8+o] = fmaf(d * d, inv2, t[di*8+o]);
            }
        }
    }
    #pragma unroll
    for (int k = 0; k < K; k++) g_aff2p[p*K + k] = -t[k] * (1.f/3.f);
}

// ---------------- full-res affinity + softmax -> g_aff (pixel-major) ----------
__global__ __launch_bounds__(256) void aff1_kernel(const float* __restrict__ imgs) {
    __shared__ float sh[56*80];
    const int tx = threadIdx.x, ty = threadIdx.y;
    const int tid = ty * 32 + tx;
    const int gx = blockIdx.x * 32 + tx;
    const int gy = blockIdx.y * 8  + ty;
    const int oy = (int)blockIdx.y * 8  - 24;
    const int ox = (int)blockIdx.x * 32 - 24;
    const int cbase = (ty + 24) * 80 + (tx + 24);

    float t[K];
    #pragma unroll
    for (int k = 0; k < K; k++) t[k] = 0.f;

    const int DD[6] = {1, 2, 4, 8, 12, 24};
    const int DY[8] = {-1,-1,-1, 0, 0, 1, 1, 1};
    const int DX[8] = {-1, 0, 1,-1, 1,-1, 0, 1};

    for (int c = 0; c < 3; c++) {
        __syncthreads();
        const float* im = imgs + c * HW;
        {
            int r = tid / 80, col = tid - r * 80;
            for (int i = tid; i < 56*80; i += 256) {
                sh[i] = im[clampi(oy + r, 0, H-1) * W + clampi(ox + col, 0, W-1)];
                r += 3; col += 16;
                if (col >= 80) { col -= 80; r++; }
            }
        }
        __syncthreads();
        float ctr = sh[cbase];
        float sum = 0.f, ss = 0.f;
        #pragma unroll
        for (int di = 0; di < 6; di++) {
            #pragma unroll
            for (int o = 0; o < 8; o++) {
                float v = sh[cbase + DY[o]*DD[di]*80 + DX[o]*DD[di]];
                sum += v; ss = fmaf(v, v, ss);
            }
        }
        float mean = sum * (1.f/48.f);
        float var  = fmaxf((ss - sum * mean) * (1.f/47.f), 0.f);
        float inv  = 1.f / ((sqrtf(var) + EPSF) * W1F);
        float inv2 = inv * inv;
        #pragma unroll
        for (int di = 0; di < 6; di++) {
            #pragma unroll
            for (int o = 0; o < 8; o++) {
                float v = sh[cbase + DY[o]*DD[di]*80 + DX[o]*DD[di]];
                float d = v - ctr;
                t[di*8+o] = fmaf(d * d, inv2, t[di*8+o]);
            }
        }
    }
    // softmax over k of (-t/3)
    float mx = -1e30f;
    #pragma unroll
    for (int k = 0; k < K; k++) { t[k] = -t[k] * (1.f/3.f); mx = fmaxf(mx, t[k]); }
    float es = 0.f;
    #pragma unroll
    for (int k = 0; k < K; k++) { t[k] = expf(t[k] - mx); es += t[k]; }
    float inv = 1.f / es;

    float4* dst = (float4*)(g_aff + ((size_t)(gy * W + gx)) * K);
    #pragma unroll
    for (int i = 0; i < 12; i++) {
        float4 v;
        v.x = t[4*i+0] * inv; v.y = t[4*i+1] * inv;
        v.z = t[4*i+2] * inv; v.w = t[4*i+3] * inv;
        dst[i] = v;
    }
}

// ------- upsample aff2 67->224, softmax, add (+ pos) into g_aff ---------------
__global__ void aff2up_kernel() {
    int p = blockIdx.x * blockDim.x + threadIdx.x;
    if (p >= HW) return;
    int y = p / W, x = p - y * W;
    float fy = (float)y * (66.f / 223.f);
    int iy = (int)fy; float wy = fy - (float)iy; int iy1 = min(iy + 1, 66);
    float fx = (float)x * (66.f / 223.f);
    int ix = (int)fx; float wx = fx - (float)ix; int ix1 = min(ix + 1, 66);
    float w00 = (1.f-wy)*(1.f-wx), w01 = (1.f-wy)*wx;
    float w10 = wy*(1.f-wx),       w11 = wy*wx;

    const float4* c00 = (const float4*)(g_aff2p + (size_t)(iy *W2+ix )*K);
    const float4* c01 = (const float4*)(g_aff2p + (size_t)(iy *W2+ix1)*K);
    const float4* c10 = (const float4*)(g_aff2p + (size_t)(iy1*W2+ix )*K);
    const float4* c11 = (const float4*)(g_aff2p + (size_t)(iy1*W2+ix1)*K);

    float a[K];
    #pragma unroll
    for (int i = 0; i < 12; i++) {
        float4 q0 = c00[i], q1 = c01[i], q2 = c10[i], q3 = c11[i];
        a[4*i+0] = q0.x*w00 + q1.x*w01 + q2.x*w10 + q3.x*w11;
        a[4*i+1] = q0.y*w00 + q1.y*w01 + q2.y*w10 + q3.y*w11;
        a[4*i+2] = q0.z*w00 + q1.z*w01 + q2.z*w10 + q3.z*w11;
        a[4*i+3] = q0.w*w00 + q1.w*w01 + q2.w*w10 + q3.w*w11;
    }
    float mx = -1e30f;
    #pragma unroll
    for (int k = 0; k < K; k++) mx = fmaxf(mx, a[k]);
    float es = 0.f;
    #pragma unroll
    for (int k = 0; k < K; k++) { a[k] = expf(a[k] - mx); es += a[k]; }
    float inv = 1.f / es;

    float4* dst = (float4*)(g_aff + (size_t)p * K);
    const float4* pp = (const float4*)g_pos;
    #pragma unroll
    for (int i = 0; i < 12; i++) {
        float4 t = dst[i];
        float4 pv = pp[i];
        t.x += a[4*i+0]*inv + pv.x;
        t.y += a[4*i+1]*inv + pv.y;
        t.z += a[4*i+2]*inv + pv.z;
        t.w += a[4*i+3]*inv + pv.w;
        dst[i] = t;
    }
}

// ---------------- one propagation iteration ----------------------------------
// grid (7, 28, 3): 32x8 pixel tile, 7 channels per z-slice.
__global__ __launch_bounds__(256) void iter_kernel(const float* __restrict__ src,
                                                   float* __restrict__ dst) {
    __shared__ float sh[56*80];
    const int tx = threadIdx.x, ty = threadIdx.y;
    const int tid = ty * 32 + tx;
    const int gx = blockIdx.x * 32 + tx;
    const int gy = blockIdx.y * 8  + ty;
    const int oy = (int)blockIdx.y * 8  - 24;
    const int ox = (int)blockIdx.x * 32 - 24;
    const int p  = gy * W + gx;
    const int c0 = blockIdx.z * 7;

    float aff[K];
    const float4* ap = (const float4*)(g_aff + (size_t)p * K);
    #pragma unroll
    for (int i = 0; i < 12; i++) {
        float4 v = ap[i];
        aff[4*i+0] = v.x; aff[4*i+1] = v.y; aff[4*i+2] = v.z; aff[4*i+3] = v.w;
    }
    const int cbase = (ty + 24) * 80 + (tx + 24);
    const int DD[6] = {1, 2, 4, 8, 12, 24};
    const int DY[8] = {-1,-1,-1, 0, 0, 1, 1, 1};
    const int DX[8] = {-1, 0, 1,-1, 1,-1, 0, 1};

    for (int c = c0; c < c0 + 7; c++) {
        __syncthreads();
        const float* m = src + (size_t)c * HW;
        {
            int r = tid / 80, col = tid - (tid / 80) * 80;
            for (int i = tid; i < 56*80; i += 256) {
                sh[i] = m[clampi(oy + r, 0, H-1) * W + clampi(ox + col, 0, W-1)];
                r += 3; col += 16;
                if (col >= 80) { col -= 80; r++; }
            }
        }
        __syncthreads();
        float acc = 0.f;
        #pragma unroll
        for (int di = 0; di < 6; di++) {
            #pragma unroll
            for (int o = 0; o < 8; o++) {
                acc = fmaf(aff[di*8+o], sh[cbase + DY[o]*DD[di]*80 + DX[o]*DD[di]], acc);
            }
        }
        dst[(size_t)c * HW + p] = acc;
    }
}

// ---------------- launch ------------------------------------------------------
extern "C" void kernel_launch(void* const* d_in, const int* in_sizes, int n_in,
                              void* d_out, int out_size) {
    const float* imgs  = (const float*)d_in[0];
    const float* masks = (const float*)d_in[1];
    if (n_in >= 2 && in_sizes[0] == C*MH*MW) {  // defensive input-order check
        const float* t = imgs; imgs = masks; masks = t;
    }
    float *buf0, *buf1;
    cudaGetSymbolAddress((void**)&buf0, g_buf0);
    cudaGetSymbolAddress((void**)&buf1, g_buf1);

    pos_kernel<<<1, 32>>>();
    upmask_kernel<<<(C*HW + 255)/256, 256>>>(masks);
    downimg_kernel<<<(3*HW2 + 255)/256, 256>>>(imgs);
    aff2_kernel<<<(HW2 + 127)/128, 128>>>();

    dim3 blk(32, 8);
    aff1_kernel<<<dim3(7, 28), blk>>>(imgs);
    aff2up_kernel<<<(HW + 255)/256, 256>>>();

    const float* src = buf0;
    for (int i = 0; i < 10; i++) {
        float* dst = (i == 9) ? (float*)d_out : ((i & 1) ? buf0 : buf1);
        iter_kernel<<<dim3(7, 28, 3), blk>>>(src, dst);
        src = dst;
    }
}

// round 2
// speedup vs baseline: 1.1927x; 1.1927x over previous
#include <cuda_runtime.h>
#include <math.h>

#define H   224
#define W   224
#define HW  (224*224)
#define C   21
#define K   48
#define H2  67
#define W2  67
#define HW2 (67*67)
#define MH  56
#define MW  56
#define EPSF 1e-8f
#define W1F  0.3f

// ---------------- device scratch (no allocations allowed) ----------------
__device__ __align__(16) float g_buf0[C*HW];
__device__ __align__(16) float g_buf1[C*HW];
__device__ __align__(16) float g_aff [HW*K];     // pixel-major [p][k]
__device__ __align__(16) float g_imgs2[3*HW2];
__device__ __align__(16) float g_aff2p[HW2*K];   // pixel-major [p2][k]

struct PosArr { float v[K]; };

__device__ __forceinline__ int clampi(int v, int lo, int hi) {
    return v < lo ? lo : (v > hi ? hi : v);
}

// ---------------- bilinear upsample masks 56 -> 224 into g_buf0 ----------------
__global__ void upmask_kernel(const float* __restrict__ m) {
    int idx = blockIdx.x * blockDim.x + threadIdx.x;
    if (idx >= C*HW) return;
    int c = idx / HW;
    int p = idx - c * HW;
    int y = p / W, x = p - y * W;
    float fy = (float)y * (55.f / 223.f);
    int y0 = (int)fy; float wy = fy - (float)y0; int y1 = min(y0 + 1, 55);
    float fx = (float)x * (55.f / 223.f);
    int x0 = (int)fx; float wx = fx - (float)x0; int x1 = min(x0 + 1, 55);
    const float* mc = m + c * MH * MW;
    float r0 = mc[y0*MW+x0] * (1.f - wy) + mc[y1*MW+x0] * wy;
    float r1 = mc[y0*MW+x1] * (1.f - wy) + mc[y1*MW+x1] * wy;
    g_buf0[idx] = r0 * (1.f - wx) + r1 * wx;
}

// ---------------- bilinear downsample imgs 224 -> 67 ----------------
__global__ void downimg_kernel(const float* __restrict__ imgs) {
    int idx = blockIdx.x * blockDim.x + threadIdx.x;
    if (idx >= 3*HW2) return;
    int c = idx / HW2;
    int p = idx - c * HW2;
    int y = p / W2, x = p - y * W2;
    float fy = (float)y * (223.f / 66.f);
    int y0 = (int)fy; float wy = fy - (float)y0; int y1 = min(y0 + 1, 223);
    float fx = (float)x * (223.f / 66.f);
    int x0 = (int)fx; float wx = fx - (float)x0; int x1 = min(x0 + 1, 223);
    const float* ic = imgs + c * HW;
    float r0 = ic[y0*W+x0] * (1.f - wy) + ic[y1*W+x0] * wy;
    float r1 = ic[y0*W+x1] * (1.f - wy) + ic[y1*W+x1] * wy;
    g_imgs2[idx] = r0 * (1.f - wx) + r1 * wx;
}

// Macro expanding the 8 neighbor accesses for dilation index DI against
// precomputed clamped row offsets (rm/r0v/rp) and cols (cm/x/cp).
#define NB_ADDR(o, DI) \
    ((o)==0 ? rm[DI]+cm[DI] : (o)==1 ? rm[DI]+x   : (o)==2 ? rm[DI]+cp[DI] : \
     (o)==3 ? r0v  +cm[DI] : (o)==4 ? r0v  +cp[DI] : \
     (o)==5 ? rp[DI]+cm[DI] : (o)==6 ? rp[DI]+x   :            rp[DI]+cp[DI])

// ---------------- low-res affinity (no W1, no softmax yet), pixel-major out ----
__global__ __launch_bounds__(128, 4) void aff2_kernel() {
    int p = blockIdx.x * blockDim.x + threadIdx.x;
    if (p >= HW2) return;
    int y = p / W2, x = p - y * W2;
    const int DD[6] = {1, 2, 4, 8, 12, 24};
    int rm[6], rp[6], cm[6], cp[6];
    #pragma unroll
    for (int di = 0; di < 6; di++) {
        int d = DD[di];
        rm[di] = max(y - d, 0) * W2;
        rp[di] = min(y + d, H2-1) * W2;
        cm[di] = max(x - d, 0);
        cp[di] = min(x + d, W2-1);
    }
    int r0v = y * W2;

    float t[K];
    #pragma unroll
    for (int k = 0; k < K; k++) t[k] = 0.f;

    for (int c = 0; c < 3; c++) {
        const float* __restrict__ im = g_imgs2 + c * HW2;
        float ctr = im[p];
        float sum = 0.f, ss = 0.f;
        #pragma unroll
        for (int di = 0; di < 6; di++) {
            #pragma unroll
            for (int o = 0; o < 8; o++) {
                float v = im[NB_ADDR(o, di)];
                sum += v; ss = fmaf(v, v, ss);
            }
        }
        float mean = sum * (1.f/48.f);
        float var  = fmaxf((ss - sum * mean) * (1.f/47.f), 0.f);
        float inv  = 1.f / (sqrtf(var) + EPSF);
        float inv2 = inv * inv;
        #pragma unroll
        for (int di = 0; di < 6; di++) {
            #pragma unroll
            for (int o = 0; o < 8; o++) {
                float d = im[NB_ADDR(o, di)] - ctr;
                t[di*8+o] = fmaf(d * d, inv2, t[di*8+o]);
            }
        }
    }
    #pragma unroll
    for (int k = 0; k < K; k++) g_aff2p[p*K + k] = -t[k] * (1.f/3.f);
}

// ---------------- full-res affinity + softmax -> g_aff (pixel-major) ----------
__global__ __launch_bounds__(256, 2) void aff1_kernel(const float* __restrict__ imgs) {
    const int tx = threadIdx.x, ty = threadIdx.y;
    const int x = blockIdx.x * 32 + tx;
    const int y = blockIdx.y * 8  + ty;
    const int p = y * W + x;
    const int DD[6] = {1, 2, 4, 8, 12, 24};
    int rm[6], rp[6], cm[6], cp[6];
    #pragma unroll
    for (int di = 0; di < 6; di++) {
        int d = DD[di];
        rm[di] = max(y - d, 0) * W;
        rp[di] = min(y + d, H-1) * W;
        cm[di] = max(x - d, 0);
        cp[di] = min(x + d, W-1);
    }
    int r0v = y * W;

    float t[K];
    #pragma unroll
    for (int k = 0; k < K; k++) t[k] = 0.f;

    for (int c = 0; c < 3; c++) {
        const float* __restrict__ im = imgs + c * HW;
        float ctr = im[p];
        float sum = 0.f, ss = 0.f;
        #pragma unroll
        for (int di = 0; di < 6; di++) {
            #pragma unroll
            for (int o = 0; o < 8; o++) {
                float v = im[NB_ADDR(o, di)];
                sum += v; ss = fmaf(v, v, ss);
            }
        }
        float mean = sum * (1.f/48.f);
        float var  = fmaxf((ss - sum * mean) * (1.f/47.f), 0.f);
        float inv  = 1.f / ((sqrtf(var) + EPSF) * W1F);
        float inv2 = inv * inv;
        #pragma unroll
        for (int di = 0; di < 6; di++) {
            #pragma unroll
            for (int o = 0; o < 8; o++) {
                float d = im[NB_ADDR(o, di)] - ctr;
                t[di*8+o] = fmaf(d * d, inv2, t[di*8+o]);
            }
        }
    }
    // softmax over k of (-t/3)
    float mx = -1e30f;
    #pragma unroll
    for (int k = 0; k < K; k++) { t[k] = -t[k] * (1.f/3.f); mx = fmaxf(mx, t[k]); }
    float es = 0.f;
    #pragma unroll
    for (int k = 0; k < K; k++) { t[k] = __expf(t[k] - mx); es += t[k]; }
    float inv = 1.f / es;

    float4* dst = (float4*)(g_aff + (size_t)p * K);
    #pragma unroll
    for (int i = 0; i < 12; i++) {
        float4 v;
        v.x = t[4*i+0] * inv; v.y = t[4*i+1] * inv;
        v.z = t[4*i+2] * inv; v.w = t[4*i+3] * inv;
        dst[i] = v;
    }
}

// ------- upsample aff2 67->224, softmax, add (+ host-computed pos) ------------
__global__ __launch_bounds__(256, 2) void aff2up_kernel(PosArr pos) {
    int p = blockIdx.x * blockDim.x + threadIdx.x;
    if (p >= HW) return;
    int y = p / W, x = p - y * W;
    float fy = (float)y * (66.f / 223.f);
    int iy = (int)fy; float wy = fy - (float)iy; int iy1 = min(iy + 1, 66);
    float fx = (float)x * (66.f / 223.f);
    int ix = (int)fx; float wx = fx - (float)ix; int ix1 = min(ix + 1, 66);
    float w00 = (1.f-wy)*(1.f-wx), w01 = (1.f-wy)*wx;
    float w10 = wy*(1.f-wx),       w11 = wy*wx;

    const float4* c00 = (const float4*)(g_aff2p + (size_t)(iy *W2+ix )*K);
    const float4* c01 = (const float4*)(g_aff2p + (size_t)(iy *W2+ix1)*K);
    const float4* c10 = (const float4*)(g_aff2p + (size_t)(iy1*W2+ix )*K);
    const float4* c11 = (const float4*)(g_aff2p + (size_t)(iy1*W2+ix1)*K);

    float a[K];
    #pragma unroll
    for (int i = 0; i < 12; i++) {
        float4 q0 = c00[i], q1 = c01[i], q2 = c10[i], q3 = c11[i];
        a[4*i+0] = q0.x*w00 + q1.x*w01 + q2.x*w10 + q3.x*w11;
        a[4*i+1] = q0.y*w00 + q1.y*w01 + q2.y*w10 + q3.y*w11;
        a[4*i+2] = q0.z*w00 + q1.z*w01 + q2.z*w10 + q3.z*w11;
        a[4*i+3] = q0.w*w00 + q1.w*w01 + q2.w*w10 + q3.w*w11;
    }
    float mx = -1e30f;
    #pragma unroll
    for (int k = 0; k < K; k++) mx = fmaxf(mx, a[k]);
    float es = 0.f;
    #pragma unroll
    for (int k = 0; k < K; k++) { a[k] = __expf(a[k] - mx); es += a[k]; }
    float inv = 1.f / es;

    float4* dst = (float4*)(g_aff + (size_t)p * K);
    const float4* pp = (const float4*)pos.v;
    #pragma unroll
    for (int i = 0; i < 12; i++) {
        float4 t = dst[i];
        float4 pv = pp[i];
        t.x += a[4*i+0]*inv + pv.x;
        t.y += a[4*i+1]*inv + pv.y;
        t.z += a[4*i+2]*inv + pv.z;
        t.w += a[4*i+3]*inv + pv.w;
        dst[i] = t;
    }
}

// ---------------- one propagation iteration (LDG-direct, no smem) -------------
// grid (7, 28, 3): 32x8 pixel tile, 7 channels per z-slice.
__global__ __launch_bounds__(256, 2) void iter_kernel(const float* __restrict__ src,
                                                      float* __restrict__ dst) {
    const int tx = threadIdx.x, ty = threadIdx.y;
    const int x = blockIdx.x * 32 + tx;
    const int y = blockIdx.y * 8  + ty;
    const int p = y * W + x;
    const int c0 = blockIdx.z * 7;

    // per-pixel affinity (48 floats, reused across 7 channels)
    float aff[K];
    {
        const float4* ap = (const float4*)(g_aff + (size_t)p * K);
        #pragma unroll
        for (int i = 0; i < 12; i++) {
            float4 v = ap[i];
            aff[4*i+0] = v.x; aff[4*i+1] = v.y; aff[4*i+2] = v.z; aff[4*i+3] = v.w;
        }
    }

    const int DD[6] = {1, 2, 4, 8, 12, 24};
    int rm[6], rp[6], cm[6], cp[6];
    #pragma unroll
    for (int di = 0; di < 6; di++) {
        int d = DD[di];
        rm[di] = max(y - d, 0) * W;
        rp[di] = min(y + d, H-1) * W;
        cm[di] = max(x - d, 0);
        cp[di] = min(x + d, W-1);
    }
    const int r0v = y * W;

    const float* __restrict__ m = src + (size_t)c0 * HW;
    float* __restrict__ o = dst + (size_t)c0 * HW + p;
    for (int c = 0; c < 7; c++) {
        float a0 = 0.f, a1 = 0.f, a2 = 0.f, a3 = 0.f;
        #pragma unroll
        for (int di = 0; di < 6; di++) {
            a0 = fmaf(aff[di*8+0], m[rm[di]+cm[di]], a0);
            a1 = fmaf(aff[di*8+1], m[rm[di]+x     ], a1);
            a2 = fmaf(aff[di*8+2], m[rm[di]+cp[di]], a2);
            a3 = fmaf(aff[di*8+3], m[r0v   +cm[di]], a3);
            a0 = fmaf(aff[di*8+4], m[r0v   +cp[di]], a0);
            a1 = fmaf(aff[di*8+5], m[rp[di]+cm[di]], a1);
            a2 = fmaf(aff[di*8+6], m[rp[di]+x     ], a2);
            a3 = fmaf(aff[di*8+7], m[rp[di]+cp[di]], a3);
        }
        *o = (a0 + a1) + (a2 + a3);
        m += HW;
        o += HW;
    }
}

// ---------------- host pos softmax --------------------------------------------
static PosArr make_pos_host() {
    const float s2 = sqrtf(2.0f);
    const float base[8] = {s2, 1.f, s2, 1.f, 1.f, s2, 1.f, s2};
    const int DD[6] = {1, 2, 4, 8, 12, 24};
    float pos[K];
    float sum = 0.f;
    for (int di = 0; di < 6; di++)
        for (int o = 0; o < 8; o++) {
            float v = base[o] * (float)DD[di];
            pos[di*8+o] = v; sum += v;
        }
    float mean = sum / 48.f, ss = 0.f;
    for (int k = 0; k < K; k++) { float d = pos[k] - mean; ss += d * d; }
    float sd = sqrtf(ss / 47.f);
    float mx = -1e30f;
    for (int k = 0; k < K; k++) {
        float t = pos[k] / ((sd + EPSF) * W1F);
        pos[k] = -t * t;
        if (pos[k] > mx) mx = pos[k];
    }
    float es = 0.f;
    for (int k = 0; k < K; k++) { pos[k] = expf(pos[k] - mx); es += pos[k]; }
    PosArr out;
    for (int k = 0; k < K; k++) out.v[k] = pos[k] / es;
    return out;
}

// ---------------- launch ------------------------------------------------------
extern "C" void kernel_launch(void* const* d_in, const int* in_sizes, int n_in,
                              void* d_out, int out_size) {
    const float* imgs  = (const float*)d_in[0];
    const float* masks = (const float*)d_in[1];
    if (n_in >= 2 && in_sizes[0] == C*MH*MW) {  // defensive input-order check
        const float* t = imgs; imgs = masks; masks = t;
    }
    float *buf0, *buf1;
    cudaGetSymbolAddress((void**)&buf0, g_buf0);
    cudaGetSymbolAddress((void**)&buf1, g_buf1);

    PosArr pos = make_pos_host();

    dim3 blk(32, 8);
    upmask_kernel<<<(C*HW + 255)/256, 256>>>(masks);            // launch 1
    downimg_kernel<<<(3*HW2 + 255)/256, 256>>>(imgs);           // launch 2
    aff2_kernel<<<(HW2 + 127)/128, 128>>>();                    // launch 3
    aff1_kernel<<<dim3(7, 28), blk>>>(imgs);                    // launch 4
    aff2up_kernel<<<(HW + 255)/256, 256>>>(pos);                // launch 5

    const float* src = buf0;
    for (int i = 0; i < 10; i++) {                              // launches 6-15
        float* dst = (i == 9) ? (float*)d_out : ((i & 1) ? buf0 : buf1);
        iter_kernel<<<dim3(7, 28, 3), blk>>>(src, dst);
        src = dst;
    }
}